// round 1
// baseline (speedup 1.0000x reference)
#include <cuda_runtime.h>

// LIF neuron forward: T=8 leaky-integrate-fire scan.
//   mem = mem + (x - mem)*0.5  == 0.5*(mem + x)
//   spike = (mem - 0.5) > 0
//   mem   = spike ? 0 : mem
// x: [T, B*C*H*W] fp32, out: spikes, same shape.
// Purely HBM-bound: 128 MiB in + 128 MiB out.

constexpr int T_STEPS = 8;

__global__ __launch_bounds__(256) void lif_kernel(
    const float4* __restrict__ x,
    float4* __restrict__ out,
    int n4)               // n4 = (B*C*H*W)/4 float4 elements per timestep
{
    int i = blockIdx.x * blockDim.x + threadIdx.x;
    if (i >= n4) return;

    // Hoist all 8 strided loads first -> max memory-level parallelism.
    float4 xv[T_STEPS];
#pragma unroll
    for (int t = 0; t < T_STEPS; t++) {
        xv[t] = x[(size_t)t * n4 + i];
    }

    float4 mem = make_float4(0.f, 0.f, 0.f, 0.f);
#pragma unroll
    for (int t = 0; t < T_STEPS; t++) {
        float4 s;

        // lane x
        mem.x = 0.5f * (mem.x + xv[t].x);
        s.x = (mem.x > 0.5f) ? 1.0f : 0.0f;
        mem.x = (mem.x > 0.5f) ? 0.0f : mem.x;
        // lane y
        mem.y = 0.5f * (mem.y + xv[t].y);
        s.y = (mem.y > 0.5f) ? 1.0f : 0.0f;
        mem.y = (mem.y > 0.5f) ? 0.0f : mem.y;
        // lane z
        mem.z = 0.5f * (mem.z + xv[t].z);
        s.z = (mem.z > 0.5f) ? 1.0f : 0.0f;
        mem.z = (mem.z > 0.5f) ? 0.0f : mem.z;
        // lane w
        mem.w = 0.5f * (mem.w + xv[t].w);
        s.w = (mem.w > 0.5f) ? 1.0f : 0.0f;
        mem.w = (mem.w > 0.5f) ? 0.0f : mem.w;

        out[(size_t)t * n4 + i] = s;
    }
}

extern "C" void kernel_launch(void* const* d_in, const int* in_sizes, int n_in,
                              void* d_out, int out_size)
{
    const float* x = (const float*)d_in[0];
    float* out = (float*)d_out;

    // Total = T * B*C*H*W elements; per-timestep slab:
    int total = in_sizes[0];            // 33,554,432
    int per_t = total / T_STEPS;        // 4,194,304 (divisible by 4)
    int n4 = per_t / 4;                 // 1,048,576 float4 per timestep

    int threads = 256;
    int blocks = (n4 + threads - 1) / threads;

    lif_kernel<<<blocks, threads>>>(
        (const float4*)x, (float4*)out, n4);
}

// round 3
// speedup vs baseline: 1.0120x; 1.0120x over previous
#include <cuda_runtime.h>

// LIF neuron forward: T=8 leaky-integrate-fire scan. Pure streaming:
// 128 MiB read + 128 MiB write, zero reuse.
//
// R2 changes vs R1 (unchanged resubmit after infra failure):
//  - __launch_bounds__(256, 4): raise reg cap to 64 so ptxas keeps all 8
//    strided LDG.128 in flight (R1 compiled to 34 regs => hoist was re-rolled,
//    MLP ~3, DRAM stuck at 70.7%).
//  - __ldcs / __stcs streaming hints (evict-first; no reuse exists).

constexpr int T_STEPS = 8;

__global__ __launch_bounds__(256, 4) void lif_kernel(
    const float4* __restrict__ x,
    float4* __restrict__ out,
    int n4)               // float4 elements per timestep
{
    int i = blockIdx.x * blockDim.x + threadIdx.x;
    if (i >= n4) return;

    // All 8 strided loads issued back-to-back -> MLP = 8 per thread.
    float4 x0 = __ldcs(&x[(size_t)0 * n4 + i]);
    float4 x1 = __ldcs(&x[(size_t)1 * n4 + i]);
    float4 x2 = __ldcs(&x[(size_t)2 * n4 + i]);
    float4 x3 = __ldcs(&x[(size_t)3 * n4 + i]);
    float4 x4 = __ldcs(&x[(size_t)4 * n4 + i]);
    float4 x5 = __ldcs(&x[(size_t)5 * n4 + i]);
    float4 x6 = __ldcs(&x[(size_t)6 * n4 + i]);
    float4 x7 = __ldcs(&x[(size_t)7 * n4 + i]);

    float4 mem = make_float4(0.f, 0.f, 0.f, 0.f);

    float4 xv[T_STEPS] = {x0, x1, x2, x3, x4, x5, x6, x7};

#pragma unroll
    for (int t = 0; t < T_STEPS; t++) {
        float4 s;

        mem.x = 0.5f * (mem.x + xv[t].x);
        s.x = (mem.x > 0.5f) ? 1.0f : 0.0f;
        mem.x = (mem.x > 0.5f) ? 0.0f : mem.x;

        mem.y = 0.5f * (mem.y + xv[t].y);
        s.y = (mem.y > 0.5f) ? 1.0f : 0.0f;
        mem.y = (mem.y > 0.5f) ? 0.0f : mem.y;

        mem.z = 0.5f * (mem.z + xv[t].z);
        s.z = (mem.z > 0.5f) ? 1.0f : 0.0f;
        mem.z = (mem.z > 0.5f) ? 0.0f : mem.z;

        mem.w = 0.5f * (mem.w + xv[t].w);
        s.w = (mem.w > 0.5f) ? 1.0f : 0.0f;
        mem.w = (mem.w > 0.5f) ? 0.0f : mem.w;

        __stcs(&out[(size_t)t * n4 + i], s);
    }
}

extern "C" void kernel_launch(void* const* d_in, const int* in_sizes, int n_in,
                              void* d_out, int out_size)
{
    const float* x = (const float*)d_in[0];
    float* out = (float*)d_out;

    int total = in_sizes[0];            // 33,554,432
    int per_t = total / T_STEPS;        // 4,194,304
    int n4 = per_t / 4;                 // 1,048,576 float4 per timestep

    int threads = 256;
    int blocks = (n4 + threads - 1) / threads;   // 4096

    lif_kernel<<<blocks, threads>>>(
        (const float4*)x, (float4*)out, n4);
}